// round 17
// baseline (speedup 1.0000x reference)
#include <cuda_runtime.h>
#include <cuda_bf16.h>

// ConvThreshold: scale-adaptive 5x5 Gaussian conv over ReLU(bev_map) + mask.
//   conv[b,y,x] = sum relu(map[y+dy,x+dx]) * e1^(dy^2+dx^2),  e1 = exp(-1/(2 s^2+eps))
// R17: BARRIER-FREE warp-private tiles. Each warp loads its own 8x136 halo tile
// into a private smem region and syncs with __syncwarp() only — no
// __syncthreads, no cross-warp wait. VEC=4, RPT=4, separable weights,
// pre-sync scale/exp. Grid 6x48x4 = 1152 <= 148*8 = one wave.

#define BH 768
#define BW 768
#define NB 4

#define TX 32
#define TY 4                     // 4 warps per CTA
#define NTHR (TX * TY)           // 128
#define VEC 4
#define RPT 4                    // output rows per warp-lane
#define OW (TX * VEC)            // 128 output cols per block
#define OH (TY * RPT)            // 16 output rows per block
#define WTILE_H (RPT + 4)        // 8 rows per warp tile (y-origin = oy0-2)
#define WTILE_W (OW + 8)         // 136 floats (x-origin = bx-4)
#define WTILE_W4 (WTILE_W / 4)   // 34
#define WNLOAD (WTILE_H * WTILE_W4) // 272 float4s per warp

__global__ __launch_bounds__(NTHR, 8) void conv_threshold_kernel(
    const float* __restrict__ bev_map,
    const float* __restrict__ bev_scale,
    float* __restrict__ out_conv,
    float* __restrict__ out_mask)
{
    __shared__ float wtile[TY][WTILE_H][WTILE_W];   // 4 x 8 x 136 x 4B = 17.4 KB

    const int bx = blockIdx.x * OW;
    const int by = blockIdx.y * OH;
    const int b  = blockIdx.z;
    const int lane = threadIdx.x;
    const int ty   = threadIdx.y;                   // warp id in CTA

    const float* m = bev_map + (size_t)b * BH * BW;

    const int oy0 = by + ty * RPT;                  // first output row of this warp
    const int ty0 = oy0 - 2;                        // warp tile y-origin

    // ---- prefetch per-lane scales FIRST (DRAM latency overlaps tile fill) ----
    const int gx = bx + lane * VEC;
    const size_t obase = (size_t)b * BH * BW + (size_t)oy0 * BW + gx;
    float4 s4[RPT];
#pragma unroll
    for (int o = 0; o < RPT; o++)
        s4[o] = __ldg(reinterpret_cast<const float4*>(&bev_scale[obase + (size_t)o * BW]));

    // ---- warp-private tile fill: rows [oy0-2, oy0+6) x cols [bx-4, bx+132) ----
    const bool winterior = (bx >= 4) && (bx + OW + 4 <= BW) &&
                           (ty0 >= 0) && (ty0 + WTILE_H <= BH);
    if (winterior) {
#pragma unroll
        for (int it = 0; it < 9; it++) {
            const int idx = lane + it * TX;
            if (idx < WNLOAD) {
                const int ly  = idx / WTILE_W4;
                const int lxv = idx - ly * WTILE_W4;
                float4 v = *reinterpret_cast<const float4*>(
                    &m[(size_t)(ty0 + ly) * BW + (bx - 4 + lxv * 4)]);
                v.x = fmaxf(v.x, 0.0f); v.y = fmaxf(v.y, 0.0f);
                v.z = fmaxf(v.z, 0.0f); v.w = fmaxf(v.w, 0.0f);
                *reinterpret_cast<float4*>(&wtile[ty][ly][lxv * 4]) = v;
            }
        }
    } else {
#pragma unroll
        for (int it = 0; it < 9; it++) {
            const int idx = lane + it * TX;
            if (idx < WNLOAD) {
                const int ly  = idx / WTILE_W4;
                const int lxv = idx - ly * WTILE_W4;
                const int gy  = ty0 + ly;
                const int gx0 = bx - 4 + lxv * 4;
                float4 v;
                if ((unsigned)gy < BH && gx0 >= 0 && gx0 + 3 < BW) {
                    v = *reinterpret_cast<const float4*>(&m[(size_t)gy * BW + gx0]);
                } else {
                    const float* row = &m[(size_t)gy * BW];
                    v.x = ((unsigned)gy < BH && (unsigned)(gx0 + 0) < BW) ? row[gx0 + 0] : 0.0f;
                    v.y = ((unsigned)gy < BH && (unsigned)(gx0 + 1) < BW) ? row[gx0 + 1] : 0.0f;
                    v.z = ((unsigned)gy < BH && (unsigned)(gx0 + 2) < BW) ? row[gx0 + 2] : 0.0f;
                    v.w = ((unsigned)gy < BH && (unsigned)(gx0 + 3) < BW) ? row[gx0 + 3] : 0.0f;
                }
                v.x = fmaxf(v.x, 0.0f); v.y = fmaxf(v.y, 0.0f);
                v.z = fmaxf(v.z, 0.0f); v.w = fmaxf(v.w, 0.0f);
                *reinterpret_cast<float4*>(&wtile[ty][ly][lxv * 4]) = v;
            }
        }
    }

    // ---- weight exp math BEFORE the warp sync (overlaps fill latency) ----
    float e1w[RPT][VEC], e4w[RPT][VEC];
#pragma unroll
    for (int o = 0; o < RPT; o++) {
#pragma unroll
        for (int p = 0; p < VEC; p++) {
            const float s = (p == 0) ? s4[o].x : (p == 1) ? s4[o].y
                          : (p == 2) ? s4[o].z : s4[o].w;
            const float e1 = __expf(-1.0f / (2.0f * s * s + 1e-6f));
            const float e2 = e1 * e1;
            e1w[o][p] = e1;
            e4w[o][p] = e2 * e2;
        }
    }

    __syncwarp();   // warp-local visibility of the private tile; no cross-warp wait

    // ---- per-lane: 4 x-pixels (gx..gx+3) x 4 y-rows (oy0..oy0+3) ----
    float acc[RPT][VEC];
#pragma unroll
    for (int o = 0; o < RPT; o++)
#pragma unroll
        for (int p = 0; p < VEC; p++) acc[o][p] = 0.0f;

    const int c0 = lane * VEC;     // pixel p tap dx -> v[2+p+dx] (tile x-origin bx-4)

#pragma unroll
    for (int r = 0; r < WTILE_H; r++) {       // 8 tile rows (tile y-origin oy0-2)
        const float4 a  = *reinterpret_cast<const float4*>(&wtile[ty][r][c0]);
        const float4 bq = *reinterpret_cast<const float4*>(&wtile[ty][r][c0 + 4]);
        const float4 c  = *reinterpret_cast<const float4*>(&wtile[ty][r][c0 + 8]);
        const float v[12] = {a.x, a.y, a.z, a.w, bq.x, bq.y, bq.z, bq.w,
                             c.x, c.y, c.z, c.w};

        // weight-independent x-pair sums, shared by all output rows
        float a04[VEC], a13[VEC], a2[VEC];
#pragma unroll
        for (int p = 0; p < VEC; p++) {
            a04[p] = v[2 + p] + v[6 + p];
            a13[p] = v[3 + p] + v[5 + p];
            a2[p]  = v[4 + p];
        }

#pragma unroll
        for (int o = 0; o < RPT; o++) {
            const int k = r - o;               // tap index for output row o
            if (k >= 0 && k <= 4) {
                const int ady = (k < 2) ? (2 - k) : (k - 2);   // |dy| in {0,1,2}
#pragma unroll
                for (int p = 0; p < VEC; p++) {
                    const float rs = fmaf(e4w[o][p], a04[p],
                                     fmaf(e1w[o][p], a13[p], a2[p]));
                    if (ady == 0)      acc[o][p] += rs;
                    else if (ady == 1) acc[o][p] = fmaf(rs, e1w[o][p], acc[o][p]);
                    else               acc[o][p] = fmaf(rs, e4w[o][p], acc[o][p]);
                }
            }
        }
    }

#pragma unroll
    for (int o = 0; o < RPT; o++) {
        float4 conv4 = make_float4(acc[o][0], acc[o][1], acc[o][2], acc[o][3]);
        float4 mask4 = make_float4(acc[o][0] >= 0.5f ? 1.0f : 0.0f,
                                   acc[o][1] >= 0.5f ? 1.0f : 0.0f,
                                   acc[o][2] >= 0.5f ? 1.0f : 0.0f,
                                   acc[o][3] >= 0.5f ? 1.0f : 0.0f);
        *reinterpret_cast<float4*>(&out_conv[obase + (size_t)o * BW]) = conv4;
        *reinterpret_cast<float4*>(&out_mask[obase + (size_t)o * BW]) = mask4;
    }
}

extern "C" void kernel_launch(void* const* d_in, const int* in_sizes, int n_in,
                              void* d_out, int out_size)
{
    const float* bev_map   = (const float*)d_in[0];
    const float* bev_scale = (const float*)d_in[1];
    float* out = (float*)d_out;

    float* out_conv = out;
    float* out_mask = out + (size_t)NB * BH * BW;

    dim3 block(TX, TY);
    dim3 grid(BW / OW, BH / OH, NB);   // 6 x 48 x 4 = 1152 blocks <= 148*8 = one wave
    conv_threshold_kernel<<<grid, block>>>(bev_map, bev_scale, out_conv, out_mask);
}